// round 13
// baseline (speedup 1.0000x reference)
#include <cuda_runtime.h>
#include <cuda_bf16.h>
#include <math.h>
#include <stdint.h>

#define NN 100000
#define EE 1600000
#define PP 262144
#define ET (EE + NN)
#define NB 98            // ceil(NN/1024)
#define NEG_SLOPE 0.2f

// ---------------- scratch (no allocations allowed) ----------------
__device__ float g_xw1[NN * 128];   // x @ W1 (fp32)
__device__ float g_out1[NN * 128];  // layer-1 aggregation output
__device__ float g_u[NN];
__device__ float g_v[NN];
__device__ float g_as1[NN * 2];
__device__ float g_ad1[NN * 2];
__device__ float g_as2[NN];
__device__ float g_ad2[NN];
__device__ float2 g_tuv[NN];        // per-node link projections (tu, tv)
__device__ int   g_deg[NN];
__device__ int   g_off[NN + 1];
__device__ int   g_cur[NN];
__device__ int   g_csr[ET];
__device__ int   g_bsum[NB];
__device__ int   g_bpre[NB];

__device__ __forceinline__ float lrelu(float v) { return v > 0.f ? v : NEG_SLOPE * v; }
__device__ __forceinline__ float to_tf32(float x) {
    float r; asm("cvt.rna.tf32.f32 %0, %1;" : "=f"(r) : "f"(x)); return r;
}

// ---------------- CSR build (R9-proven version) ----------------
__global__ void init_deg_kernel(int* deg) {
    int i = blockIdx.x * blockDim.x + threadIdx.x;
    if (i < NN) deg[i] = 0;
}

__global__ void hist_kernel(const int* __restrict__ ei, int* deg) {
    int i = blockIdx.x * blockDim.x + threadIdx.x;
    if (i < EE) atomicAdd(&deg[__ldg(&ei[EE + i])], 1);
}

__global__ __launch_bounds__(1024) void scanA_kernel(
    const int* __restrict__ deg, int* __restrict__ off, int* __restrict__ bsum)
{
    __shared__ int wsum[32];
    int tid = threadIdx.x, lane = tid & 31, wid = tid >> 5;
    int idx = blockIdx.x * 1024 + tid;
    int v = (idx < NN) ? deg[idx] + 1 : 0;   // +1 = self loop
    int x = v;
#pragma unroll
    for (int o = 1; o < 32; o <<= 1) { int t = __shfl_up_sync(0xffffffffu, x, o); if (lane >= o) x += t; }
    if (lane == 31) wsum[wid] = x;
    __syncthreads();
    if (wid == 0) {
        int w = wsum[lane];
#pragma unroll
        for (int o = 1; o < 32; o <<= 1) { int t = __shfl_up_sync(0xffffffffu, w, o); if (lane >= o) w += t; }
        wsum[lane] = w;
    }
    __syncthreads();
    int pre = (wid > 0) ? wsum[wid - 1] : 0;
    if (idx < NN) off[idx] = pre + x - v;
    if (tid == 0) bsum[blockIdx.x] = wsum[31];
}

__global__ void scanB_kernel(const int* __restrict__ bsum, int* __restrict__ bpre, int* __restrict__ off)
{
    __shared__ int ws[4];
    int tid = threadIdx.x, lane = tid & 31, wid = tid >> 5;
    int v = (tid < NB) ? bsum[tid] : 0;
    int x = v;
#pragma unroll
    for (int o = 1; o < 32; o <<= 1) { int t = __shfl_up_sync(0xffffffffu, x, o); if (lane >= o) x += t; }
    if (lane == 31) ws[wid] = x;
    __syncthreads();
    int add = 0;
#pragma unroll
    for (int j = 0; j < 4; j++) if (j < wid) add += ws[j];
    int incl = x + add;
    if (tid < NB) bpre[tid] = incl - v;
    if (tid == NB - 1) off[NN] = incl;
}

__global__ __launch_bounds__(1024) void scanC_kernel(
    int* __restrict__ off, int* __restrict__ cur, const int* __restrict__ bpre)
{
    int idx = blockIdx.x * 1024 + threadIdx.x;
    if (idx < NN) {
        int o = off[idx] + bpre[blockIdx.x];
        off[idx] = o;
        cur[idx] = o;
    }
}

__global__ void scatter_kernel(const int* __restrict__ ei, int* cur, int* __restrict__ csr) {
    int i = blockIdx.x * blockDim.x + threadIdx.x;
    if (i >= ET) return;
    int s, d;
    if (i < EE) { s = __ldg(&ei[i]); d = __ldg(&ei[EE + i]); }
    else        { s = d = i - EE; }
    int p = atomicAdd(&cur[d], 1);
    csr[p] = s;
}

// ---------------- 3xTF32 tensor-core GEMM, fused epilogues ----------------
// Y = act(X[N,128]) @ W[128,BN]; per-warp m16 x BN via mma.m16n8k8 tf32.
// Error compensation: x = hi + lo, acc = hi*hi + hi*lo + lo*hi (fp32-grade).
// A fragment (PTX): a0=A[g][t], a1=A[g+8][t], a2=A[g][t+4], a3=A[g+8][t+4].
// FUSE_LINK: additionally compute tu=(y+b2)·lw[0:BN], tv=(y+b2)·lw[BN:2BN]
//            and SKIP the feature store entirely (layer 2).
template <int BN, bool RELU_BIAS, int HEADS, bool FUSE_LINK>
__global__ __launch_bounds__(256) void gemm3x_kernel(
    const float* __restrict__ X, const float* __restrict__ W,
    const float* __restrict__ bias,
    const float* __restrict__ att_s, const float* __restrict__ att_d,
    const float* __restrict__ lw, const float* __restrict__ b2f,
    float* __restrict__ xw, float* __restrict__ aso, float* __restrict__ ado,
    float2* __restrict__ tuv,
    int nrows)
{
    constexpr int BM = 128, BK = 16, K = 128;
    constexpr int XS = BK + 4;    // 20: conflict-free A reads
    constexpr int WS = BN + 8;    // %32==8: conflict-free B reads
    constexpr int NT = BN / 8;
    __shared__ float XsH[BM * XS], XsL[BM * XS];
    __shared__ float WsH[BK * WS], WsL[BK * WS];

    int tid = threadIdx.x;
    int wid = tid >> 5, lane = tid & 31;
    int g = lane >> 2, t = lane & 3;
    int wm = wid * 16;
    int mBase = blockIdx.x * BM;

    float acc[NT][4];
#pragma unroll
    for (int nt = 0; nt < NT; nt++) { acc[nt][0] = acc[nt][1] = acc[nt][2] = acc[nt][3] = 0.f; }

    for (int k0 = 0; k0 < K; k0 += BK) {
        // X tile: 128 rows x 16 k = 512 float4 chunks, 2 per thread
#pragma unroll
        for (int it = 0; it < 2; it++) {
            int i = tid + it * 256;
            int row = i >> 2;
            int q = (i & 3) * 4;
            int gr = mBase + row;
            float4 v = make_float4(0.f, 0.f, 0.f, 0.f);
            if (gr < nrows) {
                v = *reinterpret_cast<const float4*>(X + gr * K + k0 + q);
                if (RELU_BIAS) {
                    float4 b = *reinterpret_cast<const float4*>(bias + k0 + q);
                    v.x = fmaxf(v.x + b.x, 0.f);
                    v.y = fmaxf(v.y + b.y, 0.f);
                    v.z = fmaxf(v.z + b.z, 0.f);
                    v.w = fmaxf(v.w + b.w, 0.f);
                }
            }
            float hx = to_tf32(v.x), hy = to_tf32(v.y), hz = to_tf32(v.z), hw = to_tf32(v.w);
            float* ph = XsH + row * XS + q;
            float* pl = XsL + row * XS + q;
            ph[0] = hx; ph[1] = hy; ph[2] = hz; ph[3] = hw;
            pl[0] = to_tf32(v.x - hx); pl[1] = to_tf32(v.y - hy);
            pl[2] = to_tf32(v.z - hz); pl[3] = to_tf32(v.w - hw);
        }
        // W tile: 16 x BN floats
        {
            constexpr int F4R = BN / 4;
            constexpr int WI = (BK * BN / 4 + 255) / 256;
#pragma unroll
            for (int it = 0; it < WI; it++) {
                int i = tid + it * 256;
                if (i < BK * BN / 4) {
                    int row = i / F4R;
                    int q = (i % F4R) * 4;
                    float4 v = *reinterpret_cast<const float4*>(W + (k0 + row) * BN + q);
                    float hx = to_tf32(v.x), hy = to_tf32(v.y), hz = to_tf32(v.z), hw = to_tf32(v.w);
                    float* ph = WsH + row * WS + q;
                    float* pl = WsL + row * WS + q;
                    ph[0] = hx; ph[1] = hy; ph[2] = hz; ph[3] = hw;
                    pl[0] = to_tf32(v.x - hx); pl[1] = to_tf32(v.y - hy);
                    pl[2] = to_tf32(v.z - hz); pl[3] = to_tf32(v.w - hw);
                }
            }
        }
        __syncthreads();
#pragma unroll
        for (int kk = 0; kk < BK / 8; kk++) {
            int k8 = kk * 8;
            const float* xh0 = XsH + (wm + g) * XS + k8;
            const float* xh1 = XsH + (wm + g + 8) * XS + k8;
            const float* xl0 = XsL + (wm + g) * XS + k8;
            const float* xl1 = XsL + (wm + g + 8) * XS + k8;
            uint32_t aH0 = __float_as_uint(xh0[t]);
            uint32_t aH1 = __float_as_uint(xh1[t]);
            uint32_t aH2 = __float_as_uint(xh0[t + 4]);
            uint32_t aH3 = __float_as_uint(xh1[t + 4]);
            uint32_t aL0 = __float_as_uint(xl0[t]);
            uint32_t aL1 = __float_as_uint(xl1[t]);
            uint32_t aL2 = __float_as_uint(xl0[t + 4]);
            uint32_t aL3 = __float_as_uint(xl1[t + 4]);
            const float* wh0 = WsH + (k8 + t) * WS + g;
            const float* wh1 = WsH + (k8 + t + 4) * WS + g;
            const float* wl0 = WsL + (k8 + t) * WS + g;
            const float* wl1 = WsL + (k8 + t + 4) * WS + g;
#pragma unroll
            for (int nt = 0; nt < NT; nt++) {
                uint32_t bH0 = __float_as_uint(wh0[nt * 8]);
                uint32_t bH1 = __float_as_uint(wh1[nt * 8]);
                uint32_t bL0 = __float_as_uint(wl0[nt * 8]);
                uint32_t bL1 = __float_as_uint(wl1[nt * 8]);
                asm volatile(
                    "mma.sync.aligned.m16n8k8.row.col.f32.tf32.tf32.f32 "
                    "{%0,%1,%2,%3}, {%4,%5,%6,%7}, {%8,%9}, {%0,%1,%2,%3};\n"
                    : "+f"(acc[nt][0]), "+f"(acc[nt][1]), "+f"(acc[nt][2]), "+f"(acc[nt][3])
                    : "r"(aH0), "r"(aH1), "r"(aH2), "r"(aH3), "r"(bL0), "r"(bL1));
                asm volatile(
                    "mma.sync.aligned.m16n8k8.row.col.f32.tf32.tf32.f32 "
                    "{%0,%1,%2,%3}, {%4,%5,%6,%7}, {%8,%9}, {%0,%1,%2,%3};\n"
                    : "+f"(acc[nt][0]), "+f"(acc[nt][1]), "+f"(acc[nt][2]), "+f"(acc[nt][3])
                    : "r"(aL0), "r"(aL1), "r"(aL2), "r"(aL3), "r"(bH0), "r"(bH1));
                asm volatile(
                    "mma.sync.aligned.m16n8k8.row.col.f32.tf32.tf32.f32 "
                    "{%0,%1,%2,%3}, {%4,%5,%6,%7}, {%8,%9}, {%0,%1,%2,%3};\n"
                    : "+f"(acc[nt][0]), "+f"(acc[nt][1]), "+f"(acc[nt][2]), "+f"(acc[nt][3])
                    : "r"(aH0), "r"(aH1), "r"(aH2), "r"(aH3), "r"(bH0), "r"(bH1));
            }
        }
        __syncthreads();
    }

    // ---- epilogue: alpha dots (+ link dots) from fp32 accumulators ----
    // c0,c1 = row g cols nt*8+2t, +1 ; c2,c3 = row g+8, same cols
    int row0 = mBase + wm + g;
    int row1 = row0 + 8;
    float ps0[HEADS], pd0[HEADS], ps1[HEADS], pd1[HEADS];
    float tu0 = 0.f, tv0 = 0.f, tu1 = 0.f, tv1 = 0.f;
#pragma unroll
    for (int h = 0; h < HEADS; h++) { ps0[h] = pd0[h] = ps1[h] = pd1[h] = 0.f; }
#pragma unroll
    for (int nt = 0; nt < NT; nt++) {
        int c0 = nt * 8 + 2 * t, c1 = c0 + 1;
        float s0 = __ldg(att_s + c0), s1 = __ldg(att_s + c1);
        float d0 = __ldg(att_d + c0), d1 = __ldg(att_d + c1);
        int h = (HEADS == 2) ? (nt >> 3) : 0;
        ps0[h] += acc[nt][0] * s0 + acc[nt][1] * s1;
        pd0[h] += acc[nt][0] * d0 + acc[nt][1] * d1;
        ps1[h] += acc[nt][2] * s0 + acc[nt][3] * s1;
        pd1[h] += acc[nt][2] * d0 + acc[nt][3] * d1;
        if (FUSE_LINK) {
            float bb0 = __ldg(b2f + c0), bb1 = __ldg(b2f + c1);
            float wu0 = __ldg(lw + c0), wu1 = __ldg(lw + c1);
            float wv0 = __ldg(lw + BN + c0), wv1 = __ldg(lw + BN + c1);
            float y00 = acc[nt][0] + bb0, y01 = acc[nt][1] + bb1;
            float y10 = acc[nt][2] + bb0, y11 = acc[nt][3] + bb1;
            tu0 += y00 * wu0 + y01 * wu1;
            tv0 += y00 * wv0 + y01 * wv1;
            tu1 += y10 * wu0 + y11 * wu1;
            tv1 += y10 * wv0 + y11 * wv1;
        }
    }
#pragma unroll
    for (int o = 1; o <= 2; o <<= 1) {
#pragma unroll
        for (int h = 0; h < HEADS; h++) {
            ps0[h] += __shfl_xor_sync(0xffffffffu, ps0[h], o);
            pd0[h] += __shfl_xor_sync(0xffffffffu, pd0[h], o);
            ps1[h] += __shfl_xor_sync(0xffffffffu, ps1[h], o);
            pd1[h] += __shfl_xor_sync(0xffffffffu, pd1[h], o);
        }
        if (FUSE_LINK) {
            tu0 += __shfl_xor_sync(0xffffffffu, tu0, o);
            tv0 += __shfl_xor_sync(0xffffffffu, tv0, o);
            tu1 += __shfl_xor_sync(0xffffffffu, tu1, o);
            tv1 += __shfl_xor_sync(0xffffffffu, tv1, o);
        }
    }
    if (row0 < nrows) {
        if (!FUSE_LINK) {
            float2* dst = reinterpret_cast<float2*>(xw + row0 * BN);
#pragma unroll
            for (int nt = 0; nt < NT; nt++)
                dst[nt * 4 + t] = make_float2(acc[nt][0], acc[nt][1]);
        }
        if (t == 0) {
#pragma unroll
            for (int h = 0; h < HEADS; h++) {
                aso[HEADS * row0 + h] = ps0[h];
                ado[HEADS * row0 + h] = pd0[h];
            }
            if (FUSE_LINK) tuv[row0] = make_float2(tu0, tv0);
        }
    }
    if (row1 < nrows) {
        if (!FUSE_LINK) {
            float2* dst = reinterpret_cast<float2*>(xw + row1 * BN);
#pragma unroll
            for (int nt = 0; nt < NT; nt++)
                dst[nt * 4 + t] = make_float2(acc[nt][2], acc[nt][3]);
        }
        if (t == 0) {
#pragma unroll
            for (int h = 0; h < HEADS; h++) {
                aso[HEADS * row1 + h] = ps1[h];
                ado[HEADS * row1 + h] = pd1[h];
            }
            if (FUSE_LINK) tuv[row1] = make_float2(tu1, tv1);
        }
    }
}

// ---------------- aggregation 1: warp per destination node (fp32 gather) ----
__global__ __launch_bounds__(256) void agg1_kernel(
    const int* __restrict__ off, const int* __restrict__ csr,
    const float* __restrict__ asrc, const float* __restrict__ adst,
    const float* __restrict__ xw, float* __restrict__ out)
{
    int n = (blockIdx.x * blockDim.x + threadIdx.x) >> 5;
    int lane = threadIdx.x & 31;
    if (n >= NN) return;
    int beg = off[n], end = off[n + 1];
    float2 adv = ((const float2*)adst)[n];
    float ad0 = adv.x, ad1 = adv.y;

    float m0 = -INFINITY, s0 = 0.f, m1 = -INFINITY, s1 = 0.f;
    for (int i = beg + lane; i < end; i += 32) {
        int sx = __ldg(&csr[i]);
        float2 ap = ((const float2*)asrc)[sx];
        float e0 = lrelu(ap.x + ad0);
        float e1 = lrelu(ap.y + ad1);
        float nm = fmaxf(m0, e0); s0 = s0 * __expf(m0 - nm) + __expf(e0 - nm); m0 = nm;
        nm = fmaxf(m1, e1);       s1 = s1 * __expf(m1 - nm) + __expf(e1 - nm); m1 = nm;
    }
#pragma unroll
    for (int o = 16; o; o >>= 1) {
        float om = __shfl_xor_sync(0xffffffffu, m0, o);
        float os = __shfl_xor_sync(0xffffffffu, s0, o);
        float nm = fmaxf(m0, om);
        s0 = (s0 > 0.f ? s0 * __expf(m0 - nm) : 0.f) + (os > 0.f ? os * __expf(om - nm) : 0.f);
        m0 = nm;
        om = __shfl_xor_sync(0xffffffffu, m1, o);
        os = __shfl_xor_sync(0xffffffffu, s1, o);
        nm = fmaxf(m1, om);
        s1 = (s1 > 0.f ? s1 * __expf(m1 - nm) : 0.f) + (os > 0.f ? os * __expf(om - nm) : 0.f);
        m1 = nm;
    }
    int head = lane >> 4;
    float ad = head ? ad1 : ad0;
    float mm = head ? m1 : m0;
    float inv = 1.f / (head ? s1 : s0);

    float4 accA = make_float4(0.f, 0.f, 0.f, 0.f);
    float4 accB = make_float4(0.f, 0.f, 0.f, 0.f);
    const float4* xwv = (const float4*)xw;
    int i = beg;
    for (; i + 1 < end; i += 2) {
        int sA = __ldg(&csr[i]);
        int sB = __ldg(&csr[i + 1]);
        float2 apA = ((const float2*)asrc)[sA];
        float2 apB = ((const float2*)asrc)[sB];
        float4 vA = __ldg(&xwv[sA * 32 + lane]);
        float4 vB = __ldg(&xwv[sB * 32 + lane]);
        float wA = __expf(lrelu((head ? apA.y : apA.x) + ad) - mm) * inv;
        float wB = __expf(lrelu((head ? apB.y : apB.x) + ad) - mm) * inv;
        accA.x += wA * vA.x; accA.y += wA * vA.y; accA.z += wA * vA.z; accA.w += wA * vA.w;
        accB.x += wB * vB.x; accB.y += wB * vB.y; accB.z += wB * vB.z; accB.w += wB * vB.w;
    }
    if (i < end) {
        int sA = __ldg(&csr[i]);
        float2 apA = ((const float2*)asrc)[sA];
        float4 vA = __ldg(&xwv[sA * 32 + lane]);
        float wA = __expf(lrelu((head ? apA.y : apA.x) + ad) - mm) * inv;
        accA.x += wA * vA.x; accA.y += wA * vA.y; accA.z += wA * vA.z; accA.w += wA * vA.w;
    }
    ((float4*)out)[n * 32 + lane] =
        make_float4(accA.x + accB.x, accA.y + accB.y, accA.z + accB.z, accA.w + accB.w);
}

// ---- aggregation 2: SCALAR softmax-weighted average of (tu, tv) ----
// u[n] = sum_j alpha_j tu[s_j]  (b2·wu folded into tu; Sum(alpha)=1)
__global__ __launch_bounds__(256) void agg2_kernel(
    const int* __restrict__ off, const int* __restrict__ csr,
    const float* __restrict__ asrc, const float* __restrict__ adst,
    const float2* __restrict__ tuv, float* __restrict__ u, float* __restrict__ v)
{
    int n = (blockIdx.x * blockDim.x + threadIdx.x) >> 5;
    int lane = threadIdx.x & 31;
    if (n >= NN) return;
    int beg = off[n], end = off[n + 1];
    float ad = adst[n];

    float m = -INFINITY, s = 0.f;
    for (int i = beg + lane; i < end; i += 32) {
        int sx = __ldg(&csr[i]);
        float e = lrelu(asrc[sx] + ad);
        float nm = fmaxf(m, e);
        s = s * __expf(m - nm) + __expf(e - nm);
        m = nm;
    }
#pragma unroll
    for (int o = 16; o; o >>= 1) {
        float om = __shfl_xor_sync(0xffffffffu, m, o);
        float os = __shfl_xor_sync(0xffffffffu, s, o);
        float nm = fmaxf(m, om);
        s = (s > 0.f ? s * __expf(m - nm) : 0.f) + (os > 0.f ? os * __expf(om - nm) : 0.f);
        m = nm;
    }
    float inv = 1.f / s;

    float su = 0.f, sv = 0.f;
    for (int i = beg + lane; i < end; i += 32) {
        int sx = __ldg(&csr[i]);
        float w = __expf(lrelu(asrc[sx] + ad) - m) * inv;
        float2 tv2 = __ldg(&tuv[sx]);
        su += w * tv2.x;
        sv += w * tv2.y;
    }
#pragma unroll
    for (int o = 16; o; o >>= 1) {
        su += __shfl_xor_sync(0xffffffffu, su, o);
        sv += __shfl_xor_sync(0xffffffffu, sv, o);
    }
    if (lane == 0) { u[n] = su; v[n] = sv; }
}

// ---------------- decode: 1 thread per candidate edge ----------------
__global__ __launch_bounds__(256) void decode_kernel(
    const int* __restrict__ pos, const int* __restrict__ neg,
    const float* __restrict__ u, const float* __restrict__ v,
    const float* __restrict__ lb, float* __restrict__ out)
{
    int t = blockIdx.x * blockDim.x + threadIdx.x;
    if (t >= 2 * PP) return;
    const int* e = (t < PP) ? pos : neg;
    int q = (t < PP) ? t : t - PP;
    int s = __ldg(&e[q]), d = __ldg(&e[PP + q]);
    out[t] = __ldg(&u[s]) + __ldg(&v[d]) + __ldg(&lb[0]);
}

// ---------------- launch (single stream) ----------------
extern "C" void kernel_launch(void* const* d_in, const int* in_sizes, int n_in,
                              void* d_out, int out_size)
{
    const float* x   = (const float*)d_in[0];
    const int*   ei  = (const int*)d_in[1];
    // d_in[2] edge_weight unused by GATConv
    const int*   pos = (const int*)d_in[3];
    const int*   neg = (const int*)d_in[4];
    const float* W1  = (const float*)d_in[5];
    const float* as1 = (const float*)d_in[6];
    const float* ad1 = (const float*)d_in[7];
    const float* b1  = (const float*)d_in[8];
    const float* W2  = (const float*)d_in[9];
    const float* as2 = (const float*)d_in[10];
    const float* ad2 = (const float*)d_in[11];
    const float* b2  = (const float*)d_in[12];
    const float* lw  = (const float*)d_in[13];
    const float* lb  = (const float*)d_in[14];
    float* out = (float*)d_out;

    float *p_xw1, *p_out1, *p_u, *p_v, *p_as1, *p_ad1, *p_as2, *p_ad2;
    float2* p_tuv;
    int *p_deg, *p_off, *p_cur, *p_csr, *p_bsum, *p_bpre;
    cudaGetSymbolAddress((void**)&p_xw1, g_xw1);
    cudaGetSymbolAddress((void**)&p_out1, g_out1);
    cudaGetSymbolAddress((void**)&p_u, g_u);
    cudaGetSymbolAddress((void**)&p_v, g_v);
    cudaGetSymbolAddress((void**)&p_as1, g_as1);
    cudaGetSymbolAddress((void**)&p_ad1, g_ad1);
    cudaGetSymbolAddress((void**)&p_as2, g_as2);
    cudaGetSymbolAddress((void**)&p_ad2, g_ad2);
    cudaGetSymbolAddress((void**)&p_tuv, g_tuv);
    cudaGetSymbolAddress((void**)&p_deg, g_deg);
    cudaGetSymbolAddress((void**)&p_off, g_off);
    cudaGetSymbolAddress((void**)&p_cur, g_cur);
    cudaGetSymbolAddress((void**)&p_csr, g_csr);
    cudaGetSymbolAddress((void**)&p_bsum, g_bsum);
    cudaGetSymbolAddress((void**)&p_bpre, g_bpre);

    // CSR build (self loops folded into scanA's +1) — R9 version
    init_deg_kernel<<<(NN + 255) / 256, 256>>>(p_deg);
    hist_kernel<<<(EE + 255) / 256, 256>>>(ei, p_deg);
    scanA_kernel<<<NB, 1024>>>(p_deg, p_off, p_bsum);
    scanB_kernel<<<1, 128>>>(p_bsum, p_bpre, p_off);
    scanC_kernel<<<NB, 1024>>>(p_off, p_cur, p_bpre);
    scatter_kernel<<<(ET + 255) / 256, 256>>>(ei, p_cur, p_csr);

    int gemm_grid = (NN + 127) / 128;

    // Layer 1: 3xTF32 GEMM + fused alpha epilogue, then aggregation
    gemm3x_kernel<128, false, 2, false><<<gemm_grid, 256>>>(
        x, W1, (const float*)nullptr, as1, ad1,
        (const float*)nullptr, (const float*)nullptr,
        p_xw1, p_as1, p_ad1, (float2*)nullptr, NN);
    agg1_kernel<<<(NN + 7) / 8, 256>>>(p_off, p_csr, p_as1, p_ad1, p_xw1, p_out1);

    // Layer 2: relu(out1+b1) fused into X load; alpha + link dots fused;
    // xw2 never materialized.
    gemm3x_kernel<64, true, 1, true><<<gemm_grid, 256>>>(
        p_out1, W2, b1, as2, ad2, lw, b2,
        (float*)nullptr, p_as2, p_ad2, p_tuv, NN);
    agg2_kernel<<<(NN + 7) / 8, 256>>>(p_off, p_csr, p_as2, p_ad2, p_tuv, p_u, p_v);

    // Link prediction
    decode_kernel<<<(2 * PP + 255) / 256, 256>>>(pos, neg, p_u, p_v, lb, out);
}

// round 14
// speedup vs baseline: 1.3944x; 1.3944x over previous
#include <cuda_runtime.h>
#include <cuda_bf16.h>
#include <math.h>
#include <stdint.h>

#define NN 100000
#define EE 1600000
#define PP 262144
#define ET (EE + NN)
#define NB 98            // ceil(NN/1024)
#define NEG_SLOPE 0.2f

// ---------------- scratch (no allocations allowed) ----------------
__device__ float g_xw1[NN * 128];   // x @ W1 (fp32)
__device__ float g_out1[NN * 128];  // layer-1 aggregation output
__device__ float g_xw2[NN * 64];    // relu(out1+b1) @ W2 (fp32)
__device__ float g_u[NN];
__device__ float g_v[NN];
__device__ float2 g_tuv[NN];        // per-node link projections (tu, tv)
__device__ float g_as1[NN * 2];
__device__ float g_ad1[NN * 2];
__device__ float g_as2[NN];
__device__ float g_ad2[NN];
__device__ int   g_deg[NN];
__device__ int   g_off[NN + 1];
__device__ int   g_cur[NN];
__device__ int   g_csr[ET];
__device__ int   g_bsum[NB];
__device__ int   g_bpre[NB];

__device__ __forceinline__ float lrelu(float v) { return v > 0.f ? v : NEG_SLOPE * v; }
__device__ __forceinline__ float to_tf32(float x) {
    float r; asm("cvt.rna.tf32.f32 %0, %1;" : "=f"(r) : "f"(x)); return r;
}

// ---------------- CSR build (R9-proven version) ----------------
__global__ void init_deg_kernel(int* deg) {
    int i = blockIdx.x * blockDim.x + threadIdx.x;
    if (i < NN) deg[i] = 0;
}

__global__ void hist_kernel(const int* __restrict__ ei, int* deg) {
    int i = blockIdx.x * blockDim.x + threadIdx.x;
    if (i < EE) atomicAdd(&deg[__ldg(&ei[EE + i])], 1);
}

__global__ __launch_bounds__(1024) void scanA_kernel(
    const int* __restrict__ deg, int* __restrict__ off, int* __restrict__ bsum)
{
    __shared__ int wsum[32];
    int tid = threadIdx.x, lane = tid & 31, wid = tid >> 5;
    int idx = blockIdx.x * 1024 + tid;
    int v = (idx < NN) ? deg[idx] + 1 : 0;   // +1 = self loop
    int x = v;
#pragma unroll
    for (int o = 1; o < 32; o <<= 1) { int t = __shfl_up_sync(0xffffffffu, x, o); if (lane >= o) x += t; }
    if (lane == 31) wsum[wid] = x;
    __syncthreads();
    if (wid == 0) {
        int w = wsum[lane];
#pragma unroll
        for (int o = 1; o < 32; o <<= 1) { int t = __shfl_up_sync(0xffffffffu, w, o); if (lane >= o) w += t; }
        wsum[lane] = w;
    }
    __syncthreads();
    int pre = (wid > 0) ? wsum[wid - 1] : 0;
    if (idx < NN) off[idx] = pre + x - v;
    if (tid == 0) bsum[blockIdx.x] = wsum[31];
}

__global__ void scanB_kernel(const int* __restrict__ bsum, int* __restrict__ bpre, int* __restrict__ off)
{
    __shared__ int ws[4];
    int tid = threadIdx.x, lane = tid & 31, wid = tid >> 5;
    int v = (tid < NB) ? bsum[tid] : 0;
    int x = v;
#pragma unroll
    for (int o = 1; o < 32; o <<= 1) { int t = __shfl_up_sync(0xffffffffu, x, o); if (lane >= o) x += t; }
    if (lane == 31) ws[wid] = x;
    __syncthreads();
    int add = 0;
#pragma unroll
    for (int j = 0; j < 4; j++) if (j < wid) add += ws[j];
    int incl = x + add;
    if (tid < NB) bpre[tid] = incl - v;
    if (tid == NB - 1) off[NN] = incl;
}

__global__ __launch_bounds__(1024) void scanC_kernel(
    int* __restrict__ off, int* __restrict__ cur, const int* __restrict__ bpre)
{
    int idx = blockIdx.x * 1024 + threadIdx.x;
    if (idx < NN) {
        int o = off[idx] + bpre[blockIdx.x];
        off[idx] = o;
        cur[idx] = o;
    }
}

__global__ void scatter_kernel(const int* __restrict__ ei, int* cur, int* __restrict__ csr) {
    int i = blockIdx.x * blockDim.x + threadIdx.x;
    if (i >= ET) return;
    int s, d;
    if (i < EE) { s = __ldg(&ei[i]); d = __ldg(&ei[EE + i]); }
    else        { s = d = i - EE; }
    int p = atomicAdd(&cur[d], 1);
    csr[p] = s;
}

// ---------------- 3xTF32 tensor-core GEMM, fused alpha epilogue, fp32 out ----
// Y = act(X[N,128]) @ W[128,BN]; per-warp m16 x BN via mma.m16n8k8 tf32.
// Error compensation: x = hi + lo, acc = hi*hi + hi*lo + lo*hi (fp32-grade).
// A fragment (PTX): a0=A[g][t], a1=A[g+8][t], a2=A[g][t+4], a3=A[g+8][t+4].
template <int BN, bool RELU_BIAS, int HEADS>
__global__ __launch_bounds__(256) void gemm3x_kernel(
    const float* __restrict__ X, const float* __restrict__ W,
    const float* __restrict__ bias,
    const float* __restrict__ att_s, const float* __restrict__ att_d,
    float* __restrict__ xw, float* __restrict__ aso, float* __restrict__ ado,
    int nrows)
{
    constexpr int BM = 128, BK = 16, K = 128;
    constexpr int XS = BK + 4;    // 20: conflict-free A reads
    constexpr int WS = BN + 8;    // %32==8: conflict-free B reads
    constexpr int NT = BN / 8;
    __shared__ float XsH[BM * XS], XsL[BM * XS];
    __shared__ float WsH[BK * WS], WsL[BK * WS];

    int tid = threadIdx.x;
    int wid = tid >> 5, lane = tid & 31;
    int g = lane >> 2, t = lane & 3;
    int wm = wid * 16;
    int mBase = blockIdx.x * BM;

    float acc[NT][4];
#pragma unroll
    for (int nt = 0; nt < NT; nt++) { acc[nt][0] = acc[nt][1] = acc[nt][2] = acc[nt][3] = 0.f; }

    for (int k0 = 0; k0 < K; k0 += BK) {
        // X tile: 128 rows x 16 k = 512 float4 chunks, 2 per thread
#pragma unroll
        for (int it = 0; it < 2; it++) {
            int i = tid + it * 256;
            int row = i >> 2;
            int q = (i & 3) * 4;
            int gr = mBase + row;
            float4 v = make_float4(0.f, 0.f, 0.f, 0.f);
            if (gr < nrows) {
                v = *reinterpret_cast<const float4*>(X + gr * K + k0 + q);
                if (RELU_BIAS) {
                    float4 b = *reinterpret_cast<const float4*>(bias + k0 + q);
                    v.x = fmaxf(v.x + b.x, 0.f);
                    v.y = fmaxf(v.y + b.y, 0.f);
                    v.z = fmaxf(v.z + b.z, 0.f);
                    v.w = fmaxf(v.w + b.w, 0.f);
                }
            }
            float hx = to_tf32(v.x), hy = to_tf32(v.y), hz = to_tf32(v.z), hw = to_tf32(v.w);
            float* ph = XsH + row * XS + q;
            float* pl = XsL + row * XS + q;
            ph[0] = hx; ph[1] = hy; ph[2] = hz; ph[3] = hw;
            pl[0] = to_tf32(v.x - hx); pl[1] = to_tf32(v.y - hy);
            pl[2] = to_tf32(v.z - hz); pl[3] = to_tf32(v.w - hw);
        }
        // W tile: 16 x BN floats
        {
            constexpr int F4R = BN / 4;
            constexpr int WI = (BK * BN / 4 + 255) / 256;
#pragma unroll
            for (int it = 0; it < WI; it++) {
                int i = tid + it * 256;
                if (i < BK * BN / 4) {
                    int row = i / F4R;
                    int q = (i % F4R) * 4;
                    float4 v = *reinterpret_cast<const float4*>(W + (k0 + row) * BN + q);
                    float hx = to_tf32(v.x), hy = to_tf32(v.y), hz = to_tf32(v.z), hw = to_tf32(v.w);
                    float* ph = WsH + row * WS + q;
                    float* pl = WsL + row * WS + q;
                    ph[0] = hx; ph[1] = hy; ph[2] = hz; ph[3] = hw;
                    pl[0] = to_tf32(v.x - hx); pl[1] = to_tf32(v.y - hy);
                    pl[2] = to_tf32(v.z - hz); pl[3] = to_tf32(v.w - hw);
                }
            }
        }
        __syncthreads();
#pragma unroll
        for (int kk = 0; kk < BK / 8; kk++) {
            int k8 = kk * 8;
            const float* xh0 = XsH + (wm + g) * XS + k8;
            const float* xh1 = XsH + (wm + g + 8) * XS + k8;
            const float* xl0 = XsL + (wm + g) * XS + k8;
            const float* xl1 = XsL + (wm + g + 8) * XS + k8;
            uint32_t aH0 = __float_as_uint(xh0[t]);
            uint32_t aH1 = __float_as_uint(xh1[t]);
            uint32_t aH2 = __float_as_uint(xh0[t + 4]);
            uint32_t aH3 = __float_as_uint(xh1[t + 4]);
            uint32_t aL0 = __float_as_uint(xl0[t]);
            uint32_t aL1 = __float_as_uint(xl1[t]);
            uint32_t aL2 = __float_as_uint(xl0[t + 4]);
            uint32_t aL3 = __float_as_uint(xl1[t + 4]);
            const float* wh0 = WsH + (k8 + t) * WS + g;
            const float* wh1 = WsH + (k8 + t + 4) * WS + g;
            const float* wl0 = WsL + (k8 + t) * WS + g;
            const float* wl1 = WsL + (k8 + t + 4) * WS + g;
#pragma unroll
            for (int nt = 0; nt < NT; nt++) {
                uint32_t bH0 = __float_as_uint(wh0[nt * 8]);
                uint32_t bH1 = __float_as_uint(wh1[nt * 8]);
                uint32_t bL0 = __float_as_uint(wl0[nt * 8]);
                uint32_t bL1 = __float_as_uint(wl1[nt * 8]);
                asm volatile(
                    "mma.sync.aligned.m16n8k8.row.col.f32.tf32.tf32.f32 "
                    "{%0,%1,%2,%3}, {%4,%5,%6,%7}, {%8,%9}, {%0,%1,%2,%3};\n"
                    : "+f"(acc[nt][0]), "+f"(acc[nt][1]), "+f"(acc[nt][2]), "+f"(acc[nt][3])
                    : "r"(aH0), "r"(aH1), "r"(aH2), "r"(aH3), "r"(bL0), "r"(bL1));
                asm volatile(
                    "mma.sync.aligned.m16n8k8.row.col.f32.tf32.tf32.f32 "
                    "{%0,%1,%2,%3}, {%4,%5,%6,%7}, {%8,%9}, {%0,%1,%2,%3};\n"
                    : "+f"(acc[nt][0]), "+f"(acc[nt][1]), "+f"(acc[nt][2]), "+f"(acc[nt][3])
                    : "r"(aL0), "r"(aL1), "r"(aL2), "r"(aL3), "r"(bH0), "r"(bH1));
                asm volatile(
                    "mma.sync.aligned.m16n8k8.row.col.f32.tf32.tf32.f32 "
                    "{%0,%1,%2,%3}, {%4,%5,%6,%7}, {%8,%9}, {%0,%1,%2,%3};\n"
                    : "+f"(acc[nt][0]), "+f"(acc[nt][1]), "+f"(acc[nt][2]), "+f"(acc[nt][3])
                    : "r"(aH0), "r"(aH1), "r"(aH2), "r"(aH3), "r"(bH0), "r"(bH1));
            }
        }
        __syncthreads();
    }

    // ---- epilogue: alpha dots (fp32) + fp32 store ----
    int row0 = mBase + wm + g;
    int row1 = row0 + 8;
    float ps0[HEADS], pd0[HEADS], ps1[HEADS], pd1[HEADS];
#pragma unroll
    for (int h = 0; h < HEADS; h++) { ps0[h] = pd0[h] = ps1[h] = pd1[h] = 0.f; }
#pragma unroll
    for (int nt = 0; nt < NT; nt++) {
        int c0 = nt * 8 + 2 * t, c1 = c0 + 1;
        float s0 = __ldg(att_s + c0), s1 = __ldg(att_s + c1);
        float d0 = __ldg(att_d + c0), d1 = __ldg(att_d + c1);
        int h = (HEADS == 2) ? (nt >> 3) : 0;
        ps0[h] += acc[nt][0] * s0 + acc[nt][1] * s1;
        pd0[h] += acc[nt][0] * d0 + acc[nt][1] * d1;
        ps1[h] += acc[nt][2] * s0 + acc[nt][3] * s1;
        pd1[h] += acc[nt][2] * d0 + acc[nt][3] * d1;
    }
#pragma unroll
    for (int h = 0; h < HEADS; h++) {
#pragma unroll
        for (int o = 1; o <= 2; o <<= 1) {
            ps0[h] += __shfl_xor_sync(0xffffffffu, ps0[h], o);
            pd0[h] += __shfl_xor_sync(0xffffffffu, pd0[h], o);
            ps1[h] += __shfl_xor_sync(0xffffffffu, ps1[h], o);
            pd1[h] += __shfl_xor_sync(0xffffffffu, pd1[h], o);
        }
    }
    if (row0 < nrows) {
        float2* dst = reinterpret_cast<float2*>(xw + row0 * BN);
#pragma unroll
        for (int nt = 0; nt < NT; nt++)
            dst[nt * 4 + t] = make_float2(acc[nt][0], acc[nt][1]);
        if (t == 0) {
#pragma unroll
            for (int h = 0; h < HEADS; h++) {
                aso[HEADS * row0 + h] = ps0[h];
                ado[HEADS * row0 + h] = pd0[h];
            }
        }
    }
    if (row1 < nrows) {
        float2* dst = reinterpret_cast<float2*>(xw + row1 * BN);
#pragma unroll
        for (int nt = 0; nt < NT; nt++)
            dst[nt * 4 + t] = make_float2(acc[nt][2], acc[nt][3]);
        if (t == 0) {
#pragma unroll
            for (int h = 0; h < HEADS; h++) {
                aso[HEADS * row1 + h] = ps1[h];
                ado[HEADS * row1 + h] = pd1[h];
            }
        }
    }
}

// ---------------- aggregation 1: warp per destination node (fp32 gather) ----
__global__ __launch_bounds__(256) void agg1_kernel(
    const int* __restrict__ off, const int* __restrict__ csr,
    const float* __restrict__ asrc, const float* __restrict__ adst,
    const float* __restrict__ xw, float* __restrict__ out)
{
    int n = (blockIdx.x * blockDim.x + threadIdx.x) >> 5;
    int lane = threadIdx.x & 31;
    if (n >= NN) return;
    int beg = off[n], end = off[n + 1];
    float2 adv = ((const float2*)adst)[n];
    float ad0 = adv.x, ad1 = adv.y;

    float m0 = -INFINITY, s0 = 0.f, m1 = -INFINITY, s1 = 0.f;
    for (int i = beg + lane; i < end; i += 32) {
        int sx = __ldg(&csr[i]);
        float2 ap = ((const float2*)asrc)[sx];
        float e0 = lrelu(ap.x + ad0);
        float e1 = lrelu(ap.y + ad1);
        float nm = fmaxf(m0, e0); s0 = s0 * __expf(m0 - nm) + __expf(e0 - nm); m0 = nm;
        nm = fmaxf(m1, e1);       s1 = s1 * __expf(m1 - nm) + __expf(e1 - nm); m1 = nm;
    }
#pragma unroll
    for (int o = 16; o; o >>= 1) {
        float om = __shfl_xor_sync(0xffffffffu, m0, o);
        float os = __shfl_xor_sync(0xffffffffu, s0, o);
        float nm = fmaxf(m0, om);
        s0 = (s0 > 0.f ? s0 * __expf(m0 - nm) : 0.f) + (os > 0.f ? os * __expf(om - nm) : 0.f);
        m0 = nm;
        om = __shfl_xor_sync(0xffffffffu, m1, o);
        os = __shfl_xor_sync(0xffffffffu, s1, o);
        nm = fmaxf(m1, om);
        s1 = (s1 > 0.f ? s1 * __expf(m1 - nm) : 0.f) + (os > 0.f ? os * __expf(om - nm) : 0.f);
        m1 = nm;
    }
    int head = lane >> 4;
    float ad = head ? ad1 : ad0;
    float mm = head ? m1 : m0;
    float inv = 1.f / (head ? s1 : s0);

    float4 accA = make_float4(0.f, 0.f, 0.f, 0.f);
    float4 accB = make_float4(0.f, 0.f, 0.f, 0.f);
    const float4* xwv = (const float4*)xw;
    int i = beg;
    for (; i + 1 < end; i += 2) {
        int sA = __ldg(&csr[i]);
        int sB = __ldg(&csr[i + 1]);
        float2 apA = ((const float2*)asrc)[sA];
        float2 apB = ((const float2*)asrc)[sB];
        float4 vA = __ldg(&xwv[sA * 32 + lane]);
        float4 vB = __ldg(&xwv[sB * 32 + lane]);
        float wA = __expf(lrelu((head ? apA.y : apA.x) + ad) - mm) * inv;
        float wB = __expf(lrelu((head ? apB.y : apB.x) + ad) - mm) * inv;
        accA.x += wA * vA.x; accA.y += wA * vA.y; accA.z += wA * vA.z; accA.w += wA * vA.w;
        accB.x += wB * vB.x; accB.y += wB * vB.y; accB.z += wB * vB.z; accB.w += wB * vB.w;
    }
    if (i < end) {
        int sA = __ldg(&csr[i]);
        float2 apA = ((const float2*)asrc)[sA];
        float4 vA = __ldg(&xwv[sA * 32 + lane]);
        float wA = __expf(lrelu((head ? apA.y : apA.x) + ad) - mm) * inv;
        accA.x += wA * vA.x; accA.y += wA * vA.y; accA.z += wA * vA.z; accA.w += wA * vA.w;
    }
    ((float4*)out)[n * 32 + lane] =
        make_float4(accA.x + accB.x, accA.y + accB.y, accA.z + accB.z, accA.w + accB.w);
}

// ---- projection: tuv[n] = ((xw2[n]+b2)·wu, (xw2[n]+b2)·wv), warp per node ----
__global__ __launch_bounds__(256) void proj_kernel(
    const float* __restrict__ xw2, const float* __restrict__ lw,
    const float* __restrict__ b2, float2* __restrict__ tuv)
{
    int n = (blockIdx.x * blockDim.x + threadIdx.x) >> 5;
    int lane = threadIdx.x & 31;
    if (n >= NN) return;
    float2 z = ((const float2*)xw2)[n * 32 + lane];
    float2 b = ((const float2*)b2)[lane];
    float zx = z.x + b.x, zy = z.y + b.y;
    float2 wu = ((const float2*)lw)[lane];
    float2 wv = ((const float2*)lw)[32 + lane];
    float tu = zx * wu.x + zy * wu.y;
    float tv = zx * wv.x + zy * wv.y;
#pragma unroll
    for (int o = 16; o; o >>= 1) {
        tu += __shfl_xor_sync(0xffffffffu, tu, o);
        tv += __shfl_xor_sync(0xffffffffu, tv, o);
    }
    if (lane == 0) tuv[n] = make_float2(tu, tv);
}

// ---- aggregation 2: scalar softmax-weighted average of (tu, tv) ----
// u[n] = sum_j alpha_j tu[s_j]  (b2·wu folded into tu; Sum(alpha)=1)
__global__ __launch_bounds__(256) void agg2_kernel(
    const int* __restrict__ off, const int* __restrict__ csr,
    const float* __restrict__ asrc, const float* __restrict__ adst,
    const float2* __restrict__ tuv, float* __restrict__ u, float* __restrict__ v)
{
    int n = (blockIdx.x * blockDim.x + threadIdx.x) >> 5;
    int lane = threadIdx.x & 31;
    if (n >= NN) return;
    int beg = off[n], end = off[n + 1];
    float ad = adst[n];

    float m = -INFINITY, s = 0.f;
    for (int i = beg + lane; i < end; i += 32) {
        int sx = __ldg(&csr[i]);
        float e = lrelu(asrc[sx] + ad);
        float nm = fmaxf(m, e);
        s = s * __expf(m - nm) + __expf(e - nm);
        m = nm;
    }
#pragma unroll
    for (int o = 16; o; o >>= 1) {
        float om = __shfl_xor_sync(0xffffffffu, m, o);
        float os = __shfl_xor_sync(0xffffffffu, s, o);
        float nm = fmaxf(m, om);
        s = (s > 0.f ? s * __expf(m - nm) : 0.f) + (os > 0.f ? os * __expf(om - nm) : 0.f);
        m = nm;
    }
    float inv = 1.f / s;

    float su = 0.f, sv = 0.f;
    for (int i = beg + lane; i < end; i += 32) {
        int sx = __ldg(&csr[i]);
        float w = __expf(lrelu(asrc[sx] + ad) - m) * inv;
        float2 tv2 = __ldg(&tuv[sx]);
        su += w * tv2.x;
        sv += w * tv2.y;
    }
#pragma unroll
    for (int o = 16; o; o >>= 1) {
        su += __shfl_xor_sync(0xffffffffu, su, o);
        sv += __shfl_xor_sync(0xffffffffu, sv, o);
    }
    if (lane == 0) { u[n] = su; v[n] = sv; }
}

// ---------------- decode: 1 thread per candidate edge ----------------
__global__ __launch_bounds__(256) void decode_kernel(
    const int* __restrict__ pos, const int* __restrict__ neg,
    const float* __restrict__ u, const float* __restrict__ v,
    const float* __restrict__ lb, float* __restrict__ out)
{
    int t = blockIdx.x * blockDim.x + threadIdx.x;
    if (t >= 2 * PP) return;
    const int* e = (t < PP) ? pos : neg;
    int q = (t < PP) ? t : t - PP;
    int s = __ldg(&e[q]), d = __ldg(&e[PP + q]);
    out[t] = __ldg(&u[s]) + __ldg(&v[d]) + __ldg(&lb[0]);
}

// ---------------- launch (single stream, R9 topology) ----------------
extern "C" void kernel_launch(void* const* d_in, const int* in_sizes, int n_in,
                              void* d_out, int out_size)
{
    const float* x   = (const float*)d_in[0];
    const int*   ei  = (const int*)d_in[1];
    // d_in[2] edge_weight unused by GATConv
    const int*   pos = (const int*)d_in[3];
    const int*   neg = (const int*)d_in[4];
    const float* W1  = (const float*)d_in[5];
    const float* as1 = (const float*)d_in[6];
    const float* ad1 = (const float*)d_in[7];
    const float* b1  = (const float*)d_in[8];
    const float* W2  = (const float*)d_in[9];
    const float* as2 = (const float*)d_in[10];
    const float* ad2 = (const float*)d_in[11];
    const float* b2  = (const float*)d_in[12];
    const float* lw  = (const float*)d_in[13];
    const float* lb  = (const float*)d_in[14];
    float* out = (float*)d_out;

    float *p_xw1, *p_out1, *p_xw2, *p_u, *p_v, *p_as1, *p_ad1, *p_as2, *p_ad2;
    float2* p_tuv;
    int *p_deg, *p_off, *p_cur, *p_csr, *p_bsum, *p_bpre;
    cudaGetSymbolAddress((void**)&p_xw1, g_xw1);
    cudaGetSymbolAddress((void**)&p_out1, g_out1);
    cudaGetSymbolAddress((void**)&p_xw2, g_xw2);
    cudaGetSymbolAddress((void**)&p_u, g_u);
    cudaGetSymbolAddress((void**)&p_v, g_v);
    cudaGetSymbolAddress((void**)&p_tuv, g_tuv);
    cudaGetSymbolAddress((void**)&p_as1, g_as1);
    cudaGetSymbolAddress((void**)&p_ad1, g_ad1);
    cudaGetSymbolAddress((void**)&p_as2, g_as2);
    cudaGetSymbolAddress((void**)&p_ad2, g_ad2);
    cudaGetSymbolAddress((void**)&p_deg, g_deg);
    cudaGetSymbolAddress((void**)&p_off, g_off);
    cudaGetSymbolAddress((void**)&p_cur, g_cur);
    cudaGetSymbolAddress((void**)&p_csr, g_csr);
    cudaGetSymbolAddress((void**)&p_bsum, g_bsum);
    cudaGetSymbolAddress((void**)&p_bpre, g_bpre);

    // CSR build (self loops folded into scanA's +1) — R9 version
    init_deg_kernel<<<(NN + 255) / 256, 256>>>(p_deg);
    hist_kernel<<<(EE + 255) / 256, 256>>>(ei, p_deg);
    scanA_kernel<<<NB, 1024>>>(p_deg, p_off, p_bsum);
    scanB_kernel<<<1, 128>>>(p_bsum, p_bpre, p_off);
    scanC_kernel<<<NB, 1024>>>(p_off, p_cur, p_bpre);
    scatter_kernel<<<(ET + 255) / 256, 256>>>(ei, p_cur, p_csr);

    int gemm_grid = (NN + 127) / 128;

    // Layer 1: 3xTF32 GEMM + fused alpha epilogue, then aggregation
    gemm3x_kernel<128, false, 2><<<gemm_grid, 256>>>(
        x, W1, (const float*)nullptr, as1, ad1, p_xw1, p_as1, p_ad1, NN);
    agg1_kernel<<<(NN + 7) / 8, 256>>>(p_off, p_csr, p_as1, p_ad1, p_xw1, p_out1);

    // Layer 2: relu(out1+b1) fused into X load; alpha epilogue fused (R9 GEMM)
    gemm3x_kernel<64, true, 1><<<gemm_grid, 256>>>(
        p_out1, W2, b1, as2, ad2, p_xw2, p_as2, p_ad2, NN);

    // Link projection per node (one coalesced pass over xw2), then scalar agg2
    proj_kernel<<<(NN + 7) / 8, 256>>>(p_xw2, lw, b2, p_tuv);
    agg2_kernel<<<(NN + 7) / 8, 256>>>(p_off, p_csr, p_as2, p_ad2, p_tuv, p_u, p_v);

    // Link prediction
    decode_kernel<<<(2 * PP + 255) / 256, 256>>>(pos, neg, p_u, p_v, lb, out);
}